// round 13
// baseline (speedup 1.0000x reference)
#include <cuda_runtime.h>
#include <cuda_fp16.h>

// Problem constants
#define NC     5
#define NB     128000
#define BATCH  8
#define NJ     15
#define HH     128
#define WW     240
#define HMPIX  (HH*WW)        // 30720 pixels per (b,cam,j) heatmap

// Tiling: 1024 threads (32 warps). smem 122.9KB forces 1 CTA/SM.
// (Measured optimum across R1-R12; all structural departures were worse.)
#define THREADS 1024
#define BPT     25            // bins per thread
#define CHUNK   (THREADS*BPT) // 25600 bins per CTA
#define NCHUNK  (NB/CHUNK)    // 5 chunks -> grid 5 x 15 x 8 = 600 CTAs

// Fused 8-byte per-(cam,bin) record (shared across all b,j):
//   .x = off (bits 0..15) | t_half_bits (bits 16..31)
//   .y = half2(vA, vB)  -- x-weights, with border cases AND the u8 scale
//                          (1/255) folded in by prep.
// Gather semantics on the u8 corner-quad heatmap:
//   quad[off] = bytes (q00, q01, q10, q11) = round(255*hm) at
//               (y,x),(y,x+1),(y+1,x),(y+1,x+1); row y+1 / col x+1 OOB -> 0.
//   p0 = (q00,q01), p1 = (q10,q11) as exact halfs via 0x6400|q bias trick
//   result = (vA,vB) . ( p0 + t*(p1-p0) )
__device__ __align__(16) uint2 g_rec[NC*NB];

__device__ __forceinline__ uint2 make_record(float gx, float gy) {
    // align_corners=True mapping
    float ix = (gx + 1.0f) * 0.5f * (float)(WW - 1);
    float iy = (gy + 1.0f) * 0.5f * (float)(HH - 1);
    float x0f = floorf(ix), y0f = floorf(iy);
    float fx = ix - x0f,    fy = iy - y0f;
    int   x0 = (int)x0f,    y0 = (int)y0f;

    // x: quad at xc provides columns (xc, xc+1); fill zero-pads col xc+1 at
    // xc==WW-1, so an invalid x1 corner contributes 0 there.
    float wA, wB; int xc;
    if (x0 >= 0 && x0 < WW) { xc = x0; wA = 1.0f - fx; wB = fx;  }
    else if (x0 == -1)      { xc = 0;  wA = fx;        wB = 0.f; }
    else                    { xc = 0;  wA = 0.f;       wB = 0.f; }

    // y folded into (t, s): interior t=fy,s=1 (quads at y=127 have zero
    // bottom bytes, handling y1 OOB); y0==-1: row 0 only, s=fy; OOB: s=0.
    float t, s; int yc;
    if (y0 >= 0 && y0 < HH) { yc = y0; t = fy;  s = 1.f; }
    else if (y0 == -1)      { yc = 0;  t = 0.f; s = fy;  }
    else                    { yc = 0;  t = 0.f; s = 0.f; }

    unsigned int off = (unsigned int)(yc * WW + xc);   // <= 30719, 15 bits
    __half th = __float2half_rn(t);
    const float inv255 = 1.0f / 255.0f;
    __half2 v = __floats2half2_rn(wA * s * inv255, wB * s * inv255);

    uint2 r;
    r.x = off | ((unsigned int)__half_as_ushort(th) << 16);
    r.y = *reinterpret_cast<unsigned int*>(&v);
    return r;
}

__global__ void prep_kernel(const float* __restrict__ grid) {
    // 4 records per thread from two float4 grid loads; stored as two
    // uint4 (STG.128 each, g_rec 16B-aligned at even indices).
    int q = blockIdx.x * 256 + threadIdx.x;   // record quad index
    if (q >= NC * NB / 4) return;
    const float4* g4 = reinterpret_cast<const float4*>(grid);
    float4 g0 = __ldg(g4 + q * 2);
    float4 g1 = __ldg(g4 + q * 2 + 1);

    uint2 r0 = make_record(g0.x, g0.y);
    uint2 r1 = make_record(g0.z, g0.w);
    uint2 r2 = make_record(g1.x, g1.y);
    uint2 r3 = make_record(g1.z, g1.w);

    uint4* dst = reinterpret_cast<uint4*>(g_rec + q * 4);
    dst[0] = make_uint4(r0.x, r0.y, r1.x, r1.y);
    dst[1] = make_uint4(r2.x, r2.y, r3.x, r3.y);
}

__device__ __forceinline__ unsigned int pack_u8x4(float4 v) {
    unsigned int q0 = __float2uint_rn(v.x * 255.f);
    unsigned int q1 = __float2uint_rn(v.y * 255.f);
    unsigned int q2 = __float2uint_rn(v.z * 255.f);
    unsigned int q3 = __float2uint_rn(v.w * 255.f);
    return q0 | (q1 << 8) | (q2 << 16) | (q3 << 24);
}

__global__ __launch_bounds__(THREADS, 1)
void sample_kernel(const float* __restrict__ heatmaps,
                   float* __restrict__ out) {
    // u8 corner-quad heatmap: HMPIX x uint32. 122,880 bytes.
    extern __shared__ unsigned int sq[];

    const int tid   = threadIdx.x;
    const int chunk = blockIdx.x;
    const int j     = blockIdx.y;
    const int b     = blockIdx.z;
    const int base  = chunk * CHUNK;

    // Fill coordinates: thread handles 4 consecutive pixels (one row) per
    // iteration. 240 % 4 == 0 -> a float4 never crosses a row.
    // Per-iteration step: p += 1024 -> +4096 pixels = 17 rows + 16 px.
    const int xstart = (tid * 4) % WW;     // first pixel's column
    const int ystart = tid / 60;           // first pixel's row (4*tid/240)

    float acc[BPT];
#pragma unroll
    for (int k = 0; k < BPT; ++k) acc[k] = 0.f;

    const __half2 BIAS = __half2half2(__ushort_as_half((unsigned short)0x6400));

    for (int cam = 0; cam < NC; ++cam) {
        __syncthreads();  // previous gathers done

        // Build u8 corner-quad heatmap in smem. Each thread: 2x LDG.128
        // (row y, row y+1), neighbor bytes via shfl, 1x STS.128 (4 quads).
        const float*  hm  = heatmaps + (((size_t)b * NC + cam) * NJ + j) * (size_t)HMPIX;
        const float4* hm4 = reinterpret_cast<const float4*>(hm);
        int x = xstart, y = ystart;
#pragma unroll
        for (int p = tid; p < HMPIX / 4; p += THREADS) {
            float4 a = __ldg(hm4 + p);
            bool has_b = (y < HH - 1);
            float4 bb = has_b ? __ldg(hm4 + p + WW / 4)
                              : make_float4(0.f, 0.f, 0.f, 0.f);

            unsigned int qa = pack_u8x4(a);
            unsigned int qb = pack_u8x4(bb);

            // Neighbor group's first bytes (pixel x+4 of rows y and y+1).
            unsigned int qa_n = __shfl_down_sync(0xffffffffu, qa, 1);
            unsigned int qb_n = __shfl_down_sync(0xffffffffu, qb, 1);
            if ((tid & 31) == 31 && x != WW - 4) {
                float a4 = __ldg(hm + 4 * p + 4);
                float b4 = has_b ? __ldg(hm + 4 * p + 4 + WW) : 0.f;
                qa_n = __float2uint_rn(a4 * 255.f);
                qb_n = __float2uint_rn(b4 * 255.f);
            }
            if (x == WW - 4) { qa_n = 0u; qb_n = 0u; }  // col 240 OOB -> 0

            // Shifted-by-one-byte rows: [a1,a2,a3,a4], [b1,b2,b3,b4]
            unsigned int qan = __byte_perm(qa, qa_n, 0x4321);
            unsigned int qbn = __byte_perm(qb, qb_n, 0x4321);

            // Interleave into quads: quad_i = (a_i, a_{i+1}, b_i, b_{i+1})
            unsigned int lo  = __byte_perm(qa,  qan, 0x5140);
            unsigned int lo2 = __byte_perm(qa,  qan, 0x7362);
            unsigned int hi  = __byte_perm(qb,  qbn, 0x5140);
            unsigned int hi2 = __byte_perm(qb,  qbn, 0x7362);
            uint4 st;
            st.x = __byte_perm(lo,  hi,  0x5410);  // (a0,a1, b0,b1)
            st.y = __byte_perm(lo,  hi,  0x7632);  // (a1,a2, b1,b2)
            st.z = __byte_perm(lo2, hi2, 0x5410);  // (a2,a3, b2,b3)
            st.w = __byte_perm(lo2, hi2, 0x7632);  // (a3,a4, b3,b4)
            *reinterpret_cast<uint4*>(sq + p * 4) = st;

            // advance (x,y): +4096 px = +17 rows +16 cols (wrap adds a row)
            x += 16; y += 17;
            if (x >= WW) { x -= WW; y += 1; }
        }
        __syncthreads();

        const uint2* __restrict__ rp = g_rec + cam * NB + base;

#pragma unroll
        for (int k = 0; k < BPT; ++k) {
            int i = k * THREADS + tid;
            uint2 r = __ldg(rp + i);
            unsigned int off = r.x & 0xFFFFu;
            // t2 = (t_half, t_half) in one PRMT (bytes 3,2 of r.x twice).
            unsigned int t2u = __byte_perm(r.x, r.x, 0x3232);
            __half2 t2  = *reinterpret_cast<const __half2*>(&t2u);
            __half2 v01 = *reinterpret_cast<const __half2*>(&r.y);

            unsigned int quad = sq[off];                       // 1x LDS.32
            unsigned int b01 = __byte_perm(quad, 0x64646464u, 0x4140);
            unsigned int b23 = __byte_perm(quad, 0x64646464u, 0x4342);
            __half2 p0b = *reinterpret_cast<const __half2*>(&b01);
            __half2 p1b = *reinterpret_cast<const __half2*>(&b23);
            __half2 d   = __hsub2(p1b, p0b);   // biases cancel; exact
            __half2 p0  = __hsub2(p0b, BIAS);  // exact integers 0..255
            __half2 pl  = __hfma2(d, t2, p0);  // row lerp
            __half2 pr  = __hmul2(pl, v01);    // x weights (incl. 1/255)
            float2 f    = __half22float2(pr);
            acc[k] += f.x + f.y;               // fp32 accumulation
        }
    }

    float* o = out + ((size_t)(b * NJ + j)) * NB + base;
#pragma unroll
    for (int k = 0; k < BPT; ++k) {
        float v = acc[k] * 0.2f;                          // mean over 5 cams
        v = fminf(fmaxf(v, 0.f), 1.f);                    // clip [0,1]
        // Streaming (evict-first) store: keep L2 for heatmaps/records.
        __stcs(o + k * THREADS + tid, v);
    }
}

extern "C" void kernel_launch(void* const* d_in, const int* in_sizes, int n_in,
                              void* d_out, int out_size) {
    const float* heatmaps = (const float*)d_in[0];
    const float* grid     = (const float*)d_in[1];
    if (n_in >= 2 && in_sizes[0] == NC * NB * 2) {
        grid     = (const float*)d_in[0];
        heatmaps = (const float*)d_in[1];
    }

    const int smem_bytes = HMPIX * (int)sizeof(unsigned int);  // 122,880 B
    cudaFuncSetAttribute(sample_kernel,
                         cudaFuncAttributeMaxDynamicSharedMemorySize, smem_bytes);

    prep_kernel<<<(NC * NB / 4 + 255) / 256, 256>>>(grid);

    dim3 g(NCHUNK, NJ, BATCH);
    sample_kernel<<<g, THREADS, smem_bytes>>>(heatmaps, (float*)d_out);
}